// round 16
// baseline (speedup 1.0000x reference)
#include <cuda_runtime.h>
#include <cuda_fp16.h>
#include <cstdint>

#define Bb 8
#define Nn 1024
#define Cc 768
#define Hh 12
#define Dd 64
#define BHh 96
#define Mm 8192
#define SCALEF 0.125f
#define EPSF 1e-8f
#define LNEPS 1e-5f

// ---------------- scratch (device globals) ----------------
__device__ __half g_qh[2][(size_t)BHh*Nn*Dd];
__device__ __half g_kh[2][(size_t)BHh*Nn*Dd];
__device__ __half g_vth[2][(size_t)BHh*Dd*Nn];  // V^T fp16: [head][d][key]
__device__ __half g_aoh[2][(size_t)Mm*Cc];
__device__ float  g_pr[2][(size_t)Mm*Cc];
__device__ __half g_wth[2][(size_t)3*Cc*Cc];
__device__ __half g_wpth[2][(size_t)Cc*Cc];
__device__ __half g_xrh[(size_t)Mm*Cc];

// ---------------- helpers ----------------
__device__ __forceinline__ uint32_t smem_u32(const void* p) {
    uint32_t a;
    asm("{ .reg .u64 t; cvta.to.shared.u64 t, %1; cvt.u32.u64 %0, t; }" : "=r"(a) : "l"(p));
    return a;
}
// exp(clamp(acc*0.125, -20, 20) - 8), FMA/ALU pipes only. Range [e^-28, e^12].
__device__ __forceinline__ float fexp8(float acc) {
    const float L2E = 1.4426950408889634f;
    const float C1 = 0.125f * L2E;
    float y = fmaf(acc, C1, -8.0f * L2E);
    y = fmaxf(y, -28.0f * L2E);
    y = fminf(y, 12.0f * L2E);
    float t = y + 12582912.0f;
    int ib = __float_as_int(t) - 0x4B400000;
    float f = y - (t - 12582912.0f);
    float p = 1.3333558146e-3f;
    p = fmaf(p, f, 9.6181291076e-3f);
    p = fmaf(p, f, 5.5504108664e-2f);
    p = fmaf(p, f, 2.4022650696e-1f);
    p = fmaf(p, f, 6.9314718056e-1f);
    p = fmaf(p, f, 1.0f);
    return __int_as_float(__float_as_int(p) + (ib << 23));
}
__device__ __forceinline__ uint32_t pack_h2(float lo, float hi) {
    half2 h = __floats2half2_rn(fminf(lo, 60000.f), fminf(hi, 60000.f));
    return *(uint32_t*)&h;
}
__device__ __forceinline__ void ldsm4(uint32_t& d0, uint32_t& d1, uint32_t& d2, uint32_t& d3, uint32_t a) {
    asm volatile("ldmatrix.sync.aligned.m8n8.x4.shared.b16 {%0,%1,%2,%3}, [%4];"
                 : "=r"(d0), "=r"(d1), "=r"(d2), "=r"(d3) : "r"(a));
}
__device__ __forceinline__ void mma16(float* c, uint32_t a0, uint32_t a1, uint32_t a2, uint32_t a3,
                                      uint32_t b0, uint32_t b1) {
    asm volatile("mma.sync.aligned.m16n8k16.row.col.f32.f16.f16.f32 "
                 "{%0,%1,%2,%3},{%4,%5,%6,%7},{%8,%9},{%0,%1,%2,%3};"
                 : "+f"(c[0]), "+f"(c[1]), "+f"(c[2]), "+f"(c[3])
                 : "r"(a0), "r"(a1), "r"(a2), "r"(a3), "r"(b0), "r"(b1));
}
#define CPA16(d, s) asm volatile("cp.async.cg.shared.global [%0], [%1], 16;" :: "r"(d), "l"(s))
#define CPCOMMIT()  asm volatile("cp.async.commit_group;" ::: "memory")
#define CPWAIT(n)   asm volatile("cp.async.wait_group %0;" :: "n"(n) : "memory")

// ====== fp16-mma mainloop, 3-stage pipeline, ONE barrier per chunk ==========
// smem: A bufs @0,16384,32768 ; B bufs @49152,65536,81920  (96KB)
__device__ __forceinline__ void gemm_h768(const __half* __restrict__ A,
                                          const __half* __restrict__ Bt,
                                          int by, int bx, uint32_t smb,
                                          float acc[2][8][4]) {
    const int tid = threadIdx.x, lane = tid & 31, wid = tid >> 5;
    const int wm = wid >> 1, wn = wid & 1;
    uint32_t dA[4], dB[4];
    const __half* sA[4];
    const __half* sB[4];
#pragma unroll
    for (int j = 0; j < 4; j++) {
        int e = tid + 256 * j;
        int m = e >> 3, kg = e & 7;
        uint32_t sw = (uint32_t)(m * 128 + ((kg * 16) ^ ((m & 7) << 4)));
        dA[j] = smb + sw;
        dB[j] = smb + 49152u + sw;
        sA[j] = A + (size_t)(by + m) * 768 + kg * 8;
        sB[j] = Bt + (size_t)(bx + m) * 768 + kg * 8;
    }
#pragma unroll
    for (int i = 0; i < 2; i++)
#pragma unroll
        for (int n = 0; n < 8; n++)
#pragma unroll
            for (int c = 0; c < 4; c++) acc[i][n][c] = 0.0f;

    // prologue: chunks 0,1
#pragma unroll
    for (int j = 0; j < 4; j++) { CPA16(dA[j], sA[j]); CPA16(dB[j], sB[j]); }
    CPCOMMIT();
#pragma unroll
    for (int j = 0; j < 4; j++) { CPA16(dA[j] + 16384u, sA[j] + 64); CPA16(dB[j] + 16384u, sB[j] + 64); }
    CPCOMMIT();

    const int al = lane & 15, seg0 = lane >> 4;
    const int aswz = (al & 7) << 4;

    for (int it = 0; it < 12; ++it) {
        if (it < 11) { CPWAIT(1); } else { CPWAIT(0); }
        __syncthreads();
        if (it + 2 < 12) {
            uint32_t ob = (uint32_t)(((it + 2) % 3) * 16384);
            int kc = (it + 2) * 64;
#pragma unroll
            for (int j = 0; j < 4; j++) { CPA16(dA[j] + ob, sA[j] + kc); CPA16(dB[j] + ob, sB[j] + kc); }
            CPCOMMIT();
        }
        uint32_t Ab = smb + (uint32_t)((it % 3) * 16384);
        uint32_t Bbf = smb + 49152u + (uint32_t)((it % 3) * 16384);
#pragma unroll
        for (int kk = 0; kk < 4; kk++) {
            int soff = (2 * kk + seg0) * 16;
            uint32_t a[2][4];
#pragma unroll
            for (int mt = 0; mt < 2; mt++) {
                int r = wm * 32 + mt * 16 + al;
                ldsm4(a[mt][0], a[mt][1], a[mt][2], a[mt][3],
                      Ab + r * 128 + (soff ^ aswz));
            }
#pragma unroll
            for (int j2 = 0; j2 < 4; j2++) {
                int r = wn * 64 + j2 * 16 + al;
                uint32_t b0, b1, b2, b3;
                ldsm4(b0, b1, b2, b3, Bbf + r * 128 + (soff ^ aswz));
#pragma unroll
                for (int mt = 0; mt < 2; mt++) {
                    mma16(acc[mt][2 * j2],     a[mt][0], a[mt][1], a[mt][2], a[mt][3], b0, b2);
                    mma16(acc[mt][2 * j2 + 1], a[mt][0], a[mt][1], a[mt][2], a[mt][3], b1, b3);
                }
            }
        }
    }
    __syncthreads();
}

// ================= 1) qkv GEMM (fp16) + scatter =============================
__global__ __launch_bounds__(256, 2) void k_qkv_mma(const __half* __restrict__ X,
                                                    const __half* __restrict__ Wt0,
                                                    const __half* __restrict__ Wt1) {
    extern __shared__ char smch[];
    uint32_t smb = smem_u32(smch);
    int br = blockIdx.z;
    const __half* Wt = br ? Wt1 : Wt0;
    int bx = blockIdx.x * 128, by = blockIdx.y * 128;
    float acc[2][8][4];
    gemm_h768(X, Wt, by, bx, smb, acc);

    int lane = threadIdx.x & 31, wid = threadIdx.x >> 5;
    int wm = wid >> 1, wn = wid & 1, g = lane >> 2, tig = lane & 3;
    int colbase = bx + wn * 64;
    int seg = colbase >> 6;
    int three = seg / 12, hseg = seg - three * 12;
    if (three == 2) {
#pragma unroll
        for (int mt = 0; mt < 2; mt++) {
            int m1 = by + wm * 32 + mt * 16 + g;
            int b1 = m1 >> 10, n1 = m1 & 1023;
            __half* vt = g_vth[br] + ((size_t)(b1 * 12 + hseg)) * 65536;
#pragma unroll
            for (int nt = 0; nt < 8; nt++) {
                int d0 = nt * 8 + 2 * tig;
                vt[(size_t)d0 * 1024 + n1]           = __float2half_rn(acc[mt][nt][0]);
                vt[(size_t)(d0 + 1) * 1024 + n1]     = __float2half_rn(acc[mt][nt][1]);
                vt[(size_t)d0 * 1024 + n1 + 8]       = __float2half_rn(acc[mt][nt][2]);
                vt[(size_t)(d0 + 1) * 1024 + n1 + 8] = __float2half_rn(acc[mt][nt][3]);
            }
        }
    } else {
        __half* base3 = (three == 0) ? g_qh[br] : g_kh[br];
#pragma unroll
        for (int mt = 0; mt < 2; mt++) {
            int m1 = by + wm * 32 + mt * 16 + g;
            int b1 = m1 >> 10, n1 = m1 & 1023;
            __half* p1 = base3 + (((size_t)(b1 * 12 + hseg)) * 1024 + n1) * 64 + 2 * tig;
            __half* p2 = p1 + (size_t)8 * 64;
#pragma unroll
            for (int nt = 0; nt < 8; nt++) {
                *(half2*)(p1 + nt * 8) = __floats2half2_rn(acc[mt][nt][0], acc[mt][nt][1]);
                *(half2*)(p2 + nt * 8) = __floats2half2_rn(acc[mt][nt][2], acc[mt][nt][3]);
            }
        }
    }
}

// ================= 2) proj GEMM (fp16) + bias ================================
__global__ __launch_bounds__(256, 2) void k_proj_mma(const __half* __restrict__ Wt0,
                                                     const __half* __restrict__ Wt1,
                                                     const float* __restrict__ bias0,
                                                     const float* __restrict__ bias1) {
    extern __shared__ char smch[];
    uint32_t smb = smem_u32(smch);
    int br = blockIdx.z;
    const __half* Wt = br ? Wt1 : Wt0;
    const float* bias = br ? bias1 : bias0;
    int bx = blockIdx.x * 128, by = blockIdx.y * 128;
    float acc[2][8][4];
    gemm_h768(g_aoh[br], Wt, by, bx, smb, acc);

    int lane = threadIdx.x & 31, wid = threadIdx.x >> 5;
    int wm = wid >> 1, wn = wid & 1, g = lane >> 2, tig = lane & 3;
    int colbase = bx + wn * 64;
#pragma unroll
    for (int mt = 0; mt < 2; mt++) {
        int m1 = by + wm * 32 + mt * 16 + g;
        float* p1 = g_pr[br] + (size_t)m1 * 768 + colbase + 2 * tig;
        float* p2 = p1 + (size_t)8 * 768;
#pragma unroll
        for (int nt = 0; nt < 8; nt++) {
            float2 bv = *(const float2*)(bias + colbase + nt * 8 + 2 * tig);
            *(float2*)(p1 + nt * 8) = make_float2(acc[mt][nt][0] + bv.x, acc[mt][nt][1] + bv.y);
            *(float2*)(p2 + nt * 8) = make_float2(acc[mt][nt][2] + bv.x, acc[mt][nt][3] + bv.y);
        }
    }
}

// ====== 3) FUSED attention: reg-E, k-split AV, 3-stage KV, 1 barrier/jt =====
// smem: Q0 @0 (8K) Q1 @8192 | K0[3] @16384 K1[3] @40960 | V0[3] @65536 V1[3] @90112
#define ASQ1 8192u
#define ASK0 16384u
#define ASK1 40960u
#define ASV0 65536u
#define ASV1 90112u
#define A_SMEM 114688

__device__ __forceinline__ void issue_kv(uint32_t smb, uint32_t sko, uint32_t svo,
                                         const __half* __restrict__ Kg,
                                         const __half* __restrict__ Vt,
                                         int j0, int tid) {
#pragma unroll
    for (int jj = 0; jj < 2; jj++) {
        int e = tid + 256 * jj;
        int n = e >> 3, kg = e & 7;
        uint32_t sw = (uint32_t)(n * 128 + ((kg * 16) ^ ((n & 7) << 4)));
        CPA16(smb + sko + sw, Kg + (size_t)(j0 + n) * 64 + kg * 8);
        CPA16(smb + svo + sw, Vt + (size_t)n * 1024 + j0 + kg * 8);
    }
}

__global__ __launch_bounds__(256, 2) void k_attn(const float* __restrict__ temp_ptr) {
    extern __shared__ char smch[];
    uint32_t smb = smem_u32(smch);
    const int head = blockIdx.y, i0 = blockIdx.x * 64;
    const int tid = threadIdx.x, lane = tid & 31, wid = tid >> 5;
    const int wm = wid & 3, h = wid >> 2;
    const __half* Qh0 = g_qh[0] + (size_t)head * 65536;
    const __half* Qh1 = g_qh[1] + (size_t)head * 65536;
    const __half* Kh0 = g_kh[0] + (size_t)head * 65536;
    const __half* Kh1 = g_kh[1] + (size_t)head * 65536;
    const __half* Vt0 = g_vth[0] + (size_t)head * 65536;
    const __half* Vt1 = g_vth[1] + (size_t)head * 65536;

#pragma unroll
    for (int j = 0; j < 4; j++) {
        int e = tid + 256 * j;
        int br = e >> 9, r = e & 511;
        int n = r >> 3, kg = r & 7;
        uint32_t dst = smb + (uint32_t)(br ? ASQ1 : 0u) + n * 128 + ((kg * 16) ^ ((n & 7) << 4));
        const __half* src = (br ? Qh1 : Qh0) + (size_t)(i0 + n) * 64 + kg * 8;
        CPA16(dst, src);
    }
    issue_kv(smb, ASK0, ASV0, Kh0, Vt0, 0, tid);
    issue_kv(smb, ASK1, ASV1, Kh1, Vt1, 0, tid);
    CPCOMMIT();
    issue_kv(smb, ASK0 + 8192u, ASV0 + 8192u, Kh0, Vt0, 64, tid);
    issue_kv(smb, ASK1 + 8192u, ASV1 + 8192u, Kh1, Vt1, 64, tid);
    CPCOMMIT();

    const int al = lane & 15, seg0 = lane >> 4;
    const int aswz = (al & 7) << 4;
    const uint32_t qA0 = smb + (wm * 16 + al) * 128;
    const uint32_t qA1 = smb + ASQ1 + (wm * 16 + al) * 128;
    const int g = lane >> 2, tig = lane & 3;

    float O0[8][4], O1[8][4];
#pragma unroll
    for (int n = 0; n < 8; n++)
#pragma unroll
        for (int c = 0; c < 4; c++) { O0[n][c] = 0.f; O1[n][c] = 0.f; }
    float z0[2] = {0.f, 0.f}, z1[2] = {0.f, 0.f}, dt[2] = {0.f, 0.f};

    for (int jt = 0; jt < 16; jt++) {
        if (jt < 15) { CPWAIT(1); } else { CPWAIT(0); }
        __syncthreads();
        if (jt + 2 < 16) {
            uint32_t nb = (uint32_t)(((jt + 2) % 3) * 8192);
            int j0 = (jt + 2) * 64;
            issue_kv(smb, ASK0 + nb, ASV0 + nb, Kh0, Vt0, j0, tid);
            issue_kv(smb, ASK1 + nb, ASV1 + nb, Kh1, Vt1, j0, tid);
            CPCOMMIT();
        }
        uint32_t cb = (uint32_t)((jt % 3) * 8192);
        const uint32_t kB0 = smb + ASK0 + cb + (h * 32 + al) * 128;
        const uint32_t kB1 = smb + ASK1 + cb + (h * 32 + al) * 128;
        const uint32_t vB0 = smb + ASV0 + cb;
        const uint32_t vB1 = smb + ASV1 + cb;

        // ---------- QK branch 0 ----------
        float acc[4][4];
#pragma unroll
        for (int n = 0; n < 4; n++)
#pragma unroll
            for (int c = 0; c < 4; c++) acc[n][c] = 0.f;
#pragma unroll
        for (int kk = 0; kk < 4; kk++) {
            int soff = ((2 * kk + seg0) * 16) ^ aswz;
            uint32_t a0, a1, a2, a3;
            ldsm4(a0, a1, a2, a3, qA0 + soff);
#pragma unroll
            for (int j2 = 0; j2 < 2; j2++) {
                uint32_t b0, b1, b2, b3;
                ldsm4(b0, b1, b2, b3, kB0 + j2 * 16 * 128 + soff);
                mma16(acc[2 * j2],     a0, a1, a2, a3, b0, b2);
                mma16(acc[2 * j2 + 1], a0, a1, a2, a3, b1, b3);
            }
        }
        uint32_t ea0[2][4];
#pragma unroll
        for (int u = 0; u < 2; u++) {
            float e00 = fexp8(acc[2 * u][0]),     e01 = fexp8(acc[2 * u][1]);
            float e02 = fexp8(acc[2 * u][2]),     e03 = fexp8(acc[2 * u][3]);
            float e10 = fexp8(acc[2 * u + 1][0]), e11 = fexp8(acc[2 * u + 1][1]);
            float e12 = fexp8(acc[2 * u + 1][2]), e13 = fexp8(acc[2 * u + 1][3]);
            z0[0] += e00 + e01 + e10 + e11;
            z0[1] += e02 + e03 + e12 + e13;
            ea0[u][0] = pack_h2(e00, e01);
            ea0[u][1] = pack_h2(e02, e03);
            ea0[u][2] = pack_h2(e10, e11);
            ea0[u][3] = pack_h2(e12, e13);
        }
        // ---------- AV branch 0 (partial over this warp's 32 keys) ----------
#pragma unroll
        for (int u = 0; u < 2; u++) {
            int koff = h * 64 + u * 32;
#pragma unroll
            for (int j2 = 0; j2 < 4; j2++) {
                uint32_t b0, b1, b2, b3;
                ldsm4(b0, b1, b2, b3, vB0 + (j2 * 16 + al) * 128 + (((koff + seg0 * 16)) ^ aswz));
                mma16(O0[2 * j2],     ea0[u][0], ea0[u][1], ea0[u][2], ea0[u][3], b0, b2);
                mma16(O0[2 * j2 + 1], ea0[u][0], ea0[u][1], ea0[u][2], ea0[u][3], b1, b3);
            }
        }
        // ---------- QK branch 1 ----------
#pragma unroll
        for (int n = 0; n < 4; n++)
#pragma unroll
            for (int c = 0; c < 4; c++) acc[n][c] = 0.f;
#pragma unroll
        for (int kk = 0; kk < 4; kk++) {
            int soff = ((2 * kk + seg0) * 16) ^ aswz;
            uint32_t a0, a1, a2, a3;
            ldsm4(a0, a1, a2, a3, qA1 + soff);
#pragma unroll
            for (int j2 = 0; j2 < 2; j2++) {
                uint32_t b0, b1, b2, b3;
                ldsm4(b0, b1, b2, b3, kB1 + j2 * 16 * 128 + soff);
                mma16(acc[2 * j2],     a0, a1, a2, a3, b0, b2);
                mma16(acc[2 * j2 + 1], a0, a1, a2, a3, b1, b3);
            }
        }
        uint32_t ea1[2][4];
#pragma unroll
        for (int u = 0; u < 2; u++) {
            float e00 = fexp8(acc[2 * u][0]),     e01 = fexp8(acc[2 * u][1]);
            float e02 = fexp8(acc[2 * u][2]),     e03 = fexp8(acc[2 * u][3]);
            float e10 = fexp8(acc[2 * u + 1][0]), e11 = fexp8(acc[2 * u + 1][1]);
            float e12 = fexp8(acc[2 * u + 1][2]), e13 = fexp8(acc[2 * u + 1][3]);
            z1[0] += e00 + e01 + e10 + e11;
            z1[1] += e02 + e03 + e12 + e13;
            float2 q0 = __half22float2(*(half2*)&ea0[u][0]);
            float2 q1 = __half22float2(*(half2*)&ea0[u][1]);
            float2 q2 = __half22float2(*(half2*)&ea0[u][2]);
            float2 q3 = __half22float2(*(half2*)&ea0[u][3]);
            dt[0] += q0.x * e00 + q0.y * e01 + q2.x * e10 + q2.y * e11;
            dt[1] += q1.x * e02 + q1.y * e03 + q3.x * e12 + q3.y * e13;
            ea1[u][0] = pack_h2(e00, e01);
            ea1[u][1] = pack_h2(e02, e03);
            ea1[u][2] = pack_h2(e10, e11);
            ea1[u][3] = pack_h2(e12, e13);
        }
        // ---------- AV branch 1 ----------
#pragma unroll
        for (int u = 0; u < 2; u++) {
            int koff = h * 64 + u * 32;
#pragma unroll
            for (int j2 = 0; j2 < 4; j2++) {
                uint32_t b0, b1, b2, b3;
                ldsm4(b0, b1, b2, b3, vB1 + (j2 * 16 + al) * 128 + (((koff + seg0 * 16)) ^ aswz));
                mma16(O1[2 * j2],     ea1[u][0], ea1[u][1], ea1[u][2], ea1[u][3], b0, b2);
                mma16(O1[2 * j2 + 1], ea1[u][0], ea1[u][1], ea1[u][2], ea1[u][3], b1, b3);
            }
        }
    }
    __syncthreads();

    // ---------- epilogue: quad-reduce, pair-combine z/dt + O, store ----------
#pragma unroll
    for (int hh2 = 0; hh2 < 2; hh2++) {
        z0[hh2] += __shfl_xor_sync(0xffffffffu, z0[hh2], 1); z0[hh2] += __shfl_xor_sync(0xffffffffu, z0[hh2], 2);
        z1[hh2] += __shfl_xor_sync(0xffffffffu, z1[hh2], 1); z1[hh2] += __shfl_xor_sync(0xffffffffu, z1[hh2], 2);
        dt[hh2] += __shfl_xor_sync(0xffffffffu, dt[hh2], 1); dt[hh2] += __shfl_xor_sync(0xffffffffu, dt[hh2], 2);
    }
    const int r1 = wm * 16 + g, r2 = r1 + 8;
    float* stage = (float*)smch;                 // 16KB O staging (Q dead)
    float* zz0 = (float*)(smch + 16384);         // K area dead
    float* zz1 = zz0 + 64;
    float* dd  = zz0 + 128;
    if (h == 0 && tig == 0) {
        zz0[r1] = z0[0]; zz0[r2] = z0[1];
        zz1[r1] = z1[0]; zz1[r2] = z1[1];
        dd[r1]  = dt[0]; dd[r2]  = dt[1];
    }
    float* sp = stage + wm * 1024;
    if (h == 0) {
#pragma unroll
        for (int nt = 0; nt < 8; nt++) {
            int dcol = nt * 8 + 2 * tig;
            sp[g * 64 + dcol]           = O0[nt][0];
            sp[g * 64 + dcol + 1]       = O0[nt][1];
            sp[(g + 8) * 64 + dcol]     = O0[nt][2];
            sp[(g + 8) * 64 + dcol + 1] = O0[nt][3];
        }
    }
    __syncthreads();
    float temp = fminf(fmaxf(*temp_ptr, 0.1f), 5.0f);
    int bidx = head / 12, hd = head - bidx * 12;
    int n1 = i0 + r1;
    float c0r[2], c1r[2];
    if (h == 1) {
#pragma unroll
        for (int hh2 = 0; hh2 < 2; hh2++) {
            int rr = hh2 ? r2 : r1;
            float a = zz0[rr] + z0[hh2];
            float b = zz1[rr] + z1[hh2];
            float d = dd[rr] + dt[hh2];
            float overlap = d / (a * b) + 2.0f * EPSF + 1024.0f * EPSF * EPSF;
            float mask = 1.0f / (1.0f + __expf(overlap * temp));
            float f = mask / (mask + EPSF);
            c0r[hh2] = f / a;
            c1r[hh2] = f / b;
        }
        __half* p1a = g_aoh[0] + ((size_t)(bidx * 1024 + n1)) * 768 + hd * 64 + 2 * tig;
        __half* p2a = g_aoh[0] + ((size_t)(bidx * 1024 + n1 + 8)) * 768 + hd * 64 + 2 * tig;
#pragma unroll
        for (int nt = 0; nt < 8; nt++) {
            int dcol = nt * 8 + 2 * tig;
            float o0 = O0[nt][0] + sp[g * 64 + dcol];
            float o1 = O0[nt][1] + sp[g * 64 + dcol + 1];
            float o2 = O0[nt][2] + sp[(g + 8) * 64 + dcol];
            float o3 = O0[nt][3] + sp[(g + 8) * 64 + dcol + 1];
            *(half2*)(p1a + nt * 8) = __floats2half2_rn(o0 * c0r[0], o1 * c0r[0]);
            *(half2*)(p2a + nt * 8) = __floats2half2_rn(o2 * c0r[1], o3 * c0r[1]);
        }
    }
    __syncthreads();
    if (h == 0) {
#pragma unroll
        for (int nt = 0; nt < 8; nt++) {
            int dcol = nt * 8 + 2 * tig;
            sp[g * 64 + dcol]           = O1[nt][0];
            sp[g * 64 + dcol + 1]       = O1[nt][1];
            sp[(g + 8) * 64 + dcol]     = O1[nt][2];
            sp[(g + 8) * 64 + dcol + 1] = O1[nt][3];
        }
    }
    __syncthreads();
    if (h == 1) {
        __half* p1b = g_aoh[1] + ((size_t)(bidx * 1024 + n1)) * 768 + hd * 64 + 2 * tig;
        __half* p2b = g_aoh[1] + ((size_t)(bidx * 1024 + n1 + 8)) * 768 + hd * 64 + 2 * tig;
#pragma unroll
        for (int nt = 0; nt < 8; nt++) {
            int dcol = nt * 8 + 2 * tig;
            float o0 = O1[nt][0] + sp[g * 64 + dcol];
            float o1 = O1[nt][1] + sp[g * 64 + dcol + 1];
            float o2 = O1[nt][2] + sp[(g + 8) * 64 + dcol];
            float o3 = O1[nt][3] + sp[(g + 8) * 64 + dcol + 1];
            *(half2*)(p1b + nt * 8) = __floats2half2_rn(o0 * c1r[0], o1 * c1r[0]);
            *(half2*)(p2b + nt * 8) = __floats2half2_rn(o2 * c1r[1], o3 * c1r[1]);
        }
    }
}

// ================= 0a) weight transpose pair -> fp16 ========================
__global__ __launch_bounds__(256) void k_tr2h(const float* __restrict__ in0,
                                              const float* __restrict__ in1,
                                              __half* __restrict__ out0,
                                              __half* __restrict__ out1, int R, int C) {
    __shared__ float t[32][33];
    const float* in = blockIdx.z ? in1 : in0;
    __half* out = blockIdx.z ? out1 : out0;
    int bx = blockIdx.x * 32, by = blockIdx.y * 32;
    int x = threadIdx.x & 31, y = threadIdx.x >> 5;
#pragma unroll
    for (int j = 0; j < 32; j += 8) t[y + j][x] = in[(size_t)(by + y + j) * C + bx + x];
    __syncthreads();
#pragma unroll
    for (int j = 0; j < 32; j += 8) out[(size_t)(bx + y + j) * R + by + x] = __float2half_rn(t[x][y + j]);
}

// ================= 0b) x -> fp16 ============================================
__global__ __launch_bounds__(256) void k_rxh(const float* __restrict__ x,
                                             __half* __restrict__ o) {
    int i = blockIdx.x * 256 + threadIdx.x;
    float4 v = ((const float4*)x)[i];
    ((half2*)o)[2 * i]     = __floats2half2_rn(v.x, v.y);
    ((half2*)o)[2 * i + 1] = __floats2half2_rn(v.z, v.w);
}

// ================= 5) LayerNorm over C=768 (both branches via y) ============
__device__ __forceinline__ float blk_reduce(float v, float* smr) {
    const unsigned full = 0xffffffffu;
#pragma unroll
    for (int o = 16; o > 0; o >>= 1) v += __shfl_xor_sync(full, v, o);
    int warp = threadIdx.x >> 5, lane = threadIdx.x & 31;
    if (lane == 0) smr[warp] = v;
    __syncthreads();
    if (warp == 0) {
        float x = (lane < 8) ? smr[lane] : 0.0f;
#pragma unroll
        for (int o = 4; o > 0; o >>= 1) x += __shfl_xor_sync(full, x, o);
        if (lane == 0) smr[0] = x;
    }
    __syncthreads();
    float r = smr[0];
    __syncthreads();
    return r;
}

__global__ __launch_bounds__(256) void k_ln(const float* __restrict__ g0,
                                            const float* __restrict__ b0,
                                            const float* __restrict__ g1,
                                            const float* __restrict__ b1,
                                            float* __restrict__ out) {
    __shared__ float smr[32];
    int br = blockIdx.y;
    int row = blockIdx.x;
    const float* gam = br ? g1 : g0;
    const float* bet = br ? b1 : b0;
    float* o = out + (size_t)br * Mm * Cc;
    const float* x = g_pr[br] + (size_t)row * Cc;
    int t = threadIdx.x;
    float v[3];
#pragma unroll
    for (int i = 0; i < 3; i++) v[i] = x[t + 256 * i];
    float s = v[0] + v[1] + v[2];
    s = blk_reduce(s, smr);
    float mu = s * (1.0f / (float)Cc);
    float ss = 0.0f;
#pragma unroll
    for (int i = 0; i < 3; i++) { float d = v[i] - mu; ss += d * d; }
    ss = blk_reduce(ss, smr);
    float inv = rsqrtf(ss * (1.0f / (float)Cc) + LNEPS);
#pragma unroll
    for (int i = 0; i < 3; i++) {
        int c = t + 256 * i;
        o[(size_t)row * Cc + c] = (v[i] - mu) * inv * gam[c] + bet[c];
    }
}

// ================= launch ==================================================
extern "C" void kernel_launch(void* const* d_in, const int* in_sizes, int n_in,
                              void* d_out, int out_size) {
    const float* x    = (const float*)d_in[0];
    const float* wq0  = (const float*)d_in[1];
    const float* wq1  = (const float*)d_in[2];
    const float* wp0  = (const float*)d_in[3];
    const float* bp0  = (const float*)d_in[4];
    const float* wp1  = (const float*)d_in[5];
    const float* bp1  = (const float*)d_in[6];
    const float* temp = (const float*)d_in[7];
    const float* g0   = (const float*)d_in[8];
    const float* b0   = (const float*)d_in[9];
    const float* g1   = (const float*)d_in[10];
    const float* b1   = (const float*)d_in[11];
    float* out = (float*)d_out;

    static __half* wt0 = nullptr; static __half* wt1 = nullptr;
    static __half* wpt0 = nullptr; static __half* wpt1 = nullptr;
    static __half* xr = nullptr;
    if (!wt0) {
        cudaGetSymbolAddress((void**)&wt0, g_wth);
        wt1 = wt0 + (size_t)3 * Cc * Cc;
        cudaGetSymbolAddress((void**)&wpt0, g_wpth);
        wpt1 = wpt0 + (size_t)Cc * Cc;
        cudaGetSymbolAddress((void**)&xr, g_xrh);
        cudaFuncSetAttribute(k_qkv_mma, cudaFuncAttributeMaxDynamicSharedMemorySize, 98304);
        cudaFuncSetAttribute(k_proj_mma, cudaFuncAttributeMaxDynamicSharedMemorySize, 98304);
        cudaFuncSetAttribute(k_attn, cudaFuncAttributeMaxDynamicSharedMemorySize, A_SMEM);
    }

    dim3 t256(256);
    k_tr2h<<<dim3(72, 24, 2), t256>>>(wq0, wq1, wt0, wt1, 768, 2304);
    k_tr2h<<<dim3(24, 24, 2), t256>>>(wp0, wp1, wpt0, wpt1, 768, 768);
    k_rxh<<<dim3(6144), t256>>>(x, xr);

    k_qkv_mma<<<dim3(18, 64, 2), t256, 98304>>>(xr, wt0, wt1);
    k_attn<<<dim3(16, BHh), t256, A_SMEM>>>(temp);
    k_proj_mma<<<dim3(6, 64, 2), t256, 98304>>>(wpt0, wpt1, bp0, bp1);
    k_ln<<<dim3(Mm, 2), t256>>>(g0, b0, g1, b1, out);
}

// round 17
// speedup vs baseline: 1.0233x; 1.0233x over previous
#include <cuda_runtime.h>
#include <cuda_fp16.h>
#include <cstdint>

#define Bb 8
#define Nn 1024
#define Cc 768
#define Hh 12
#define Dd 64
#define BHh 96
#define Mm 8192
#define SCALEF 0.125f
#define EPSF 1e-8f
#define LNEPS 1e-5f

// ---------------- scratch (device globals) ----------------
__device__ __half g_qh[2][(size_t)BHh*Nn*Dd];
__device__ __half g_kh[2][(size_t)BHh*Nn*Dd];
__device__ __half g_vth[2][(size_t)BHh*Dd*Nn];  // V^T fp16: [head][d][key]
__device__ __half g_aoh[2][(size_t)Mm*Cc];
__device__ __half g_prh[2][(size_t)Mm*Cc];      // pre-LN, fp16
__device__ __half g_wth[2][(size_t)3*Cc*Cc];
__device__ __half g_wpth[2][(size_t)Cc*Cc];
__device__ __half g_xrh[(size_t)Mm*Cc];

// ---------------- helpers ----------------
__device__ __forceinline__ uint32_t smem_u32(const void* p) {
    uint32_t a;
    asm("{ .reg .u64 t; cvta.to.shared.u64 t, %1; cvt.u32.u64 %0, t; }" : "=r"(a) : "l"(p));
    return a;
}
// exp(clamp(acc*0.125, -20, 20) - 8), FMA/ALU pipes only. Range [e^-28, e^12].
__device__ __forceinline__ float fexp8(float acc) {
    const float L2E = 1.4426950408889634f;
    const float C1 = 0.125f * L2E;
    float y = fmaf(acc, C1, -8.0f * L2E);
    y = fmaxf(y, -28.0f * L2E);
    y = fminf(y, 12.0f * L2E);
    float t = y + 12582912.0f;
    int ib = __float_as_int(t) - 0x4B400000;
    float f = y - (t - 12582912.0f);
    float p = 1.3333558146e-3f;
    p = fmaf(p, f, 9.6181291076e-3f);
    p = fmaf(p, f, 5.5504108664e-2f);
    p = fmaf(p, f, 2.4022650696e-1f);
    p = fmaf(p, f, 6.9314718056e-1f);
    p = fmaf(p, f, 1.0f);
    return __int_as_float(__float_as_int(p) + (ib << 23));
}
__device__ __forceinline__ uint32_t pack_h2(float lo, float hi) {
    half2 h = __floats2half2_rn(fminf(lo, 60000.f), fminf(hi, 60000.f));
    return *(uint32_t*)&h;
}
__device__ __forceinline__ void ldsm4(uint32_t& d0, uint32_t& d1, uint32_t& d2, uint32_t& d3, uint32_t a) {
    asm volatile("ldmatrix.sync.aligned.m8n8.x4.shared.b16 {%0,%1,%2,%3}, [%4];"
                 : "=r"(d0), "=r"(d1), "=r"(d2), "=r"(d3) : "r"(a));
}
__device__ __forceinline__ void mma16(float* c, uint32_t a0, uint32_t a1, uint32_t a2, uint32_t a3,
                                      uint32_t b0, uint32_t b1) {
    asm volatile("mma.sync.aligned.m16n8k16.row.col.f32.f16.f16.f32 "
                 "{%0,%1,%2,%3},{%4,%5,%6,%7},{%8,%9},{%0,%1,%2,%3};"
                 : "+f"(c[0]), "+f"(c[1]), "+f"(c[2]), "+f"(c[3])
                 : "r"(a0), "r"(a1), "r"(a2), "r"(a3), "r"(b0), "r"(b1));
}
#define CPA16(d, s) asm volatile("cp.async.cg.shared.global [%0], [%1], 16;" :: "r"(d), "l"(s))
#define CPCOMMIT()  asm volatile("cp.async.commit_group;" ::: "memory")
#define CPWAIT(n)   asm volatile("cp.async.wait_group %0;" :: "n"(n) : "memory")

// ====== shared fp16-mma mainloop: C[128x128] = A * B^T, K=768, k-chunk 64 ===
__device__ __forceinline__ void gemm_h768(const __half* __restrict__ A,
                                          const __half* __restrict__ Bt,
                                          int by, int bx, uint32_t smb,
                                          float acc[2][8][4]) {
    const int tid = threadIdx.x, lane = tid & 31, wid = tid >> 5;
    const int wm = wid >> 1, wn = wid & 1;
    uint32_t dA[4], dB[4];
    const __half* sA[4];
    const __half* sB[4];
#pragma unroll
    for (int j = 0; j < 4; j++) {
        int e = tid + 256 * j;
        int m = e >> 3, kg = e & 7;
        uint32_t sw = (uint32_t)(m * 128 + ((kg * 16) ^ ((m & 7) << 4)));
        dA[j] = smb + sw;
        dB[j] = smb + 32768u + sw;
        sA[j] = A + (size_t)(by + m) * 768 + kg * 8;
        sB[j] = Bt + (size_t)(bx + m) * 768 + kg * 8;
    }
#pragma unroll
    for (int i = 0; i < 2; i++)
#pragma unroll
        for (int n = 0; n < 8; n++)
#pragma unroll
            for (int c = 0; c < 4; c++) acc[i][n][c] = 0.0f;

#pragma unroll
    for (int j = 0; j < 4; j++) { CPA16(dA[j], sA[j]); CPA16(dB[j], sB[j]); }
    CPCOMMIT();

    const int al = lane & 15, seg0 = lane >> 4;
    const int aswz = (al & 7) << 4;

    for (int it = 0; it < 12; ++it) {
        if (it + 1 < 12) {
            int kc = (it + 1) * 64;
            uint32_t ob = ((it + 1) & 1) ? 16384u : 0u;
#pragma unroll
            for (int j = 0; j < 4; j++) { CPA16(dA[j] + ob, sA[j] + kc); CPA16(dB[j] + ob, sB[j] + kc); }
        }
        CPCOMMIT();
        CPWAIT(1);
        __syncthreads();
        uint32_t Ab = smb + ((it & 1) ? 16384u : 0u);
        uint32_t Bbf = smb + 32768u + ((it & 1) ? 16384u : 0u);
#pragma unroll
        for (int kk = 0; kk < 4; kk++) {
            int soff = (2 * kk + seg0) * 16;
            uint32_t a[2][4];
#pragma unroll
            for (int mt = 0; mt < 2; mt++) {
                int r = wm * 32 + mt * 16 + al;
                ldsm4(a[mt][0], a[mt][1], a[mt][2], a[mt][3],
                      Ab + r * 128 + (soff ^ aswz));
            }
#pragma unroll
            for (int j2 = 0; j2 < 4; j2++) {
                int r = wn * 64 + j2 * 16 + al;
                uint32_t b0, b1, b2, b3;
                ldsm4(b0, b1, b2, b3, Bbf + r * 128 + (soff ^ aswz));
#pragma unroll
                for (int mt = 0; mt < 2; mt++) {
                    mma16(acc[mt][2 * j2],     a[mt][0], a[mt][1], a[mt][2], a[mt][3], b0, b2);
                    mma16(acc[mt][2 * j2 + 1], a[mt][0], a[mt][1], a[mt][2], a[mt][3], b1, b3);
                }
            }
        }
        __syncthreads();
    }
}

// ================= 1) qkv GEMM (fp16) + scatter =============================
__global__ __launch_bounds__(256, 2) void k_qkv_mma(const __half* __restrict__ X,
                                                    const __half* __restrict__ Wt0,
                                                    const __half* __restrict__ Wt1) {
    extern __shared__ char smch[];
    uint32_t smb = smem_u32(smch);
    int br = blockIdx.z;
    const __half* Wt = br ? Wt1 : Wt0;
    int bx = blockIdx.x * 128, by = blockIdx.y * 128;
    float acc[2][8][4];
    gemm_h768(X, Wt, by, bx, smb, acc);

    int lane = threadIdx.x & 31, wid = threadIdx.x >> 5;
    int wm = wid >> 1, wn = wid & 1, g = lane >> 2, tig = lane & 3;
    int colbase = bx + wn * 64;
    int seg = colbase >> 6;
    int three = seg / 12, hseg = seg - three * 12;
    if (three == 2) {
#pragma unroll
        for (int mt = 0; mt < 2; mt++) {
            int m1 = by + wm * 32 + mt * 16 + g;
            int b1 = m1 >> 10, n1 = m1 & 1023;
            __half* vt = g_vth[br] + ((size_t)(b1 * 12 + hseg)) * 65536;
#pragma unroll
            for (int nt = 0; nt < 8; nt++) {
                int d0 = nt * 8 + 2 * tig;
                vt[(size_t)d0 * 1024 + n1]           = __float2half_rn(acc[mt][nt][0]);
                vt[(size_t)(d0 + 1) * 1024 + n1]     = __float2half_rn(acc[mt][nt][1]);
                vt[(size_t)d0 * 1024 + n1 + 8]       = __float2half_rn(acc[mt][nt][2]);
                vt[(size_t)(d0 + 1) * 1024 + n1 + 8] = __float2half_rn(acc[mt][nt][3]);
            }
        }
    } else {
        __half* base3 = (three == 0) ? g_qh[br] : g_kh[br];
#pragma unroll
        for (int mt = 0; mt < 2; mt++) {
            int m1 = by + wm * 32 + mt * 16 + g;
            int b1 = m1 >> 10, n1 = m1 & 1023;
            __half* p1 = base3 + (((size_t)(b1 * 12 + hseg)) * 1024 + n1) * 64 + 2 * tig;
            __half* p2 = p1 + (size_t)8 * 64;
#pragma unroll
            for (int nt = 0; nt < 8; nt++) {
                *(half2*)(p1 + nt * 8) = __floats2half2_rn(acc[mt][nt][0], acc[mt][nt][1]);
                *(half2*)(p2 + nt * 8) = __floats2half2_rn(acc[mt][nt][2], acc[mt][nt][3]);
            }
        }
    }
}

// ================= 2) proj GEMM (fp16) + bias -> fp16 pre-LN ================
__global__ __launch_bounds__(256, 2) void k_proj_mma(const __half* __restrict__ Wt0,
                                                     const __half* __restrict__ Wt1,
                                                     const float* __restrict__ bias0,
                                                     const float* __restrict__ bias1) {
    extern __shared__ char smch[];
    uint32_t smb = smem_u32(smch);
    int br = blockIdx.z;
    const __half* Wt = br ? Wt1 : Wt0;
    const float* bias = br ? bias1 : bias0;
    int bx = blockIdx.x * 128, by = blockIdx.y * 128;
    float acc[2][8][4];
    gemm_h768(g_aoh[br], Wt, by, bx, smb, acc);

    int lane = threadIdx.x & 31, wid = threadIdx.x >> 5;
    int wm = wid >> 1, wn = wid & 1, g = lane >> 2, tig = lane & 3;
    int colbase = bx + wn * 64;
#pragma unroll
    for (int mt = 0; mt < 2; mt++) {
        int m1 = by + wm * 32 + mt * 16 + g;
        __half* p1 = g_prh[br] + (size_t)m1 * 768 + colbase + 2 * tig;
        __half* p2 = p1 + (size_t)8 * 768;
#pragma unroll
        for (int nt = 0; nt < 8; nt++) {
            float2 bv = *(const float2*)(bias + colbase + nt * 8 + 2 * tig);
            *(half2*)(p1 + nt * 8) = __floats2half2_rn(acc[mt][nt][0] + bv.x, acc[mt][nt][1] + bv.y);
            *(half2*)(p2 + nt * 8) = __floats2half2_rn(acc[mt][nt][2] + bv.x, acc[mt][nt][3] + bv.y);
        }
    }
}

// ====== 3) FUSED attention: reg-E, k-split AV, double-buffered KV, occ 2 ====
// smem: Q0 @0 (8K) Q1 @8192 | K0[2] @16384 K1[2] @32768 | V0[2] @49152 V1[2] @65536
#define ASQ1 8192u
#define ASK0 16384u
#define ASK1 32768u
#define ASV0 49152u
#define ASV1 65536u
#define A_SMEM 81920

__device__ __forceinline__ void issue_kv(uint32_t smb, uint32_t sko, uint32_t svo,
                                         const __half* __restrict__ Kg,
                                         const __half* __restrict__ Vt,
                                         int j0, int tid) {
#pragma unroll
    for (int jj = 0; jj < 2; jj++) {
        int e = tid + 256 * jj;
        int n = e >> 3, kg = e & 7;
        uint32_t sw = (uint32_t)(n * 128 + ((kg * 16) ^ ((n & 7) << 4)));
        CPA16(smb + sko + sw, Kg + (size_t)(j0 + n) * 64 + kg * 8);
        CPA16(smb + svo + sw, Vt + (size_t)n * 1024 + j0 + kg * 8);
    }
}

__global__ __launch_bounds__(256, 2) void k_attn(const float* __restrict__ temp_ptr) {
    extern __shared__ char smch[];
    uint32_t smb = smem_u32(smch);
    const int head = blockIdx.y, i0 = blockIdx.x * 64;
    const int tid = threadIdx.x, lane = tid & 31, wid = tid >> 5;
    const int wm = wid & 3, h = wid >> 2;
    const __half* Qh0 = g_qh[0] + (size_t)head * 65536;
    const __half* Qh1 = g_qh[1] + (size_t)head * 65536;
    const __half* Kh0 = g_kh[0] + (size_t)head * 65536;
    const __half* Kh1 = g_kh[1] + (size_t)head * 65536;
    const __half* Vt0 = g_vth[0] + (size_t)head * 65536;
    const __half* Vt1 = g_vth[1] + (size_t)head * 65536;

#pragma unroll
    for (int j = 0; j < 4; j++) {
        int e = tid + 256 * j;
        int br = e >> 9, r = e & 511;
        int n = r >> 3, kg = r & 7;
        uint32_t dst = smb + (uint32_t)(br ? ASQ1 : 0u) + n * 128 + ((kg * 16) ^ ((n & 7) << 4));
        const __half* src = (br ? Qh1 : Qh0) + (size_t)(i0 + n) * 64 + kg * 8;
        CPA16(dst, src);
    }
    issue_kv(smb, ASK0, ASV0, Kh0, Vt0, 0, tid);
    issue_kv(smb, ASK1, ASV1, Kh1, Vt1, 0, tid);
    CPCOMMIT();
    issue_kv(smb, ASK0 + 8192u, ASV0 + 8192u, Kh0, Vt0, 64, tid);
    issue_kv(smb, ASK1 + 8192u, ASV1 + 8192u, Kh1, Vt1, 64, tid);
    CPCOMMIT();

    const int al = lane & 15, seg0 = lane >> 4;
    const int aswz = (al & 7) << 4;
    const uint32_t qA0 = smb + (wm * 16 + al) * 128;
    const uint32_t qA1 = smb + ASQ1 + (wm * 16 + al) * 128;
    const int g = lane >> 2, tig = lane & 3;

    float O0[8][4], O1[8][4];
#pragma unroll
    for (int n = 0; n < 8; n++)
#pragma unroll
        for (int c = 0; c < 4; c++) { O0[n][c] = 0.f; O1[n][c] = 0.f; }
    float z0[2] = {0.f, 0.f}, z1[2] = {0.f, 0.f}, dt[2] = {0.f, 0.f};

    for (int jt = 0; jt < 16; jt++) {
        if (jt < 15) { CPWAIT(1); } else { CPWAIT(0); }
        __syncthreads();
        uint32_t cb = (uint32_t)((jt & 1) * 8192);
        const uint32_t kB0 = smb + ASK0 + cb + (h * 32 + al) * 128;
        const uint32_t kB1 = smb + ASK1 + cb + (h * 32 + al) * 128;
        const uint32_t vB0 = smb + ASV0 + cb;
        const uint32_t vB1 = smb + ASV1 + cb;

        // ---------- QK branch 0 ----------
        float acc[4][4];
#pragma unroll
        for (int n = 0; n < 4; n++)
#pragma unroll
            for (int c = 0; c < 4; c++) acc[n][c] = 0.f;
#pragma unroll
        for (int kk = 0; kk < 4; kk++) {
            int soff = ((2 * kk + seg0) * 16) ^ aswz;
            uint32_t a0, a1, a2, a3;
            ldsm4(a0, a1, a2, a3, qA0 + soff);
#pragma unroll
            for (int j2 = 0; j2 < 2; j2++) {
                uint32_t b0, b1, b2, b3;
                ldsm4(b0, b1, b2, b3, kB0 + j2 * 16 * 128 + soff);
                mma16(acc[2 * j2],     a0, a1, a2, a3, b0, b2);
                mma16(acc[2 * j2 + 1], a0, a1, a2, a3, b1, b3);
            }
        }
        uint32_t ea0[2][4];
#pragma unroll
        for (int u = 0; u < 2; u++) {
            float e00 = fexp8(acc[2 * u][0]),     e01 = fexp8(acc[2 * u][1]);
            float e02 = fexp8(acc[2 * u][2]),     e03 = fexp8(acc[2 * u][3]);
            float e10 = fexp8(acc[2 * u + 1][0]), e11 = fexp8(acc[2 * u + 1][1]);
            float e12 = fexp8(acc[2 * u + 1][2]), e13 = fexp8(acc[2 * u + 1][3]);
            z0[0] += e00 + e01 + e10 + e11;
            z0[1] += e02 + e03 + e12 + e13;
            ea0[u][0] = pack_h2(e00, e01);
            ea0[u][1] = pack_h2(e02, e03);
            ea0[u][2] = pack_h2(e10, e11);
            ea0[u][3] = pack_h2(e12, e13);
        }
        // ---------- AV branch 0 (partial over this warp's 32 keys) ----------
#pragma unroll
        for (int u = 0; u < 2; u++) {
            int koff = h * 64 + u * 32;
#pragma unroll
            for (int j2 = 0; j2 < 4; j2++) {
                uint32_t b0, b1, b2, b3;
                ldsm4(b0, b1, b2, b3, vB0 + (j2 * 16 + al) * 128 + (((koff + seg0 * 16)) ^ aswz));
                mma16(O0[2 * j2],     ea0[u][0], ea0[u][1], ea0[u][2], ea0[u][3], b0, b2);
                mma16(O0[2 * j2 + 1], ea0[u][0], ea0[u][1], ea0[u][2], ea0[u][3], b1, b3);
            }
        }
        // ---------- QK branch 1 ----------
#pragma unroll
        for (int n = 0; n < 4; n++)
#pragma unroll
            for (int c = 0; c < 4; c++) acc[n][c] = 0.f;
#pragma unroll
        for (int kk = 0; kk < 4; kk++) {
            int soff = ((2 * kk + seg0) * 16) ^ aswz;
            uint32_t a0, a1, a2, a3;
            ldsm4(a0, a1, a2, a3, qA1 + soff);
#pragma unroll
            for (int j2 = 0; j2 < 2; j2++) {
                uint32_t b0, b1, b2, b3;
                ldsm4(b0, b1, b2, b3, kB1 + j2 * 16 * 128 + soff);
                mma16(acc[2 * j2],     a0, a1, a2, a3, b0, b2);
                mma16(acc[2 * j2 + 1], a0, a1, a2, a3, b1, b3);
            }
        }
        uint32_t ea1[2][4];
#pragma unroll
        for (int u = 0; u < 2; u++) {
            float e00 = fexp8(acc[2 * u][0]),     e01 = fexp8(acc[2 * u][1]);
            float e02 = fexp8(acc[2 * u][2]),     e03 = fexp8(acc[2 * u][3]);
            float e10 = fexp8(acc[2 * u + 1][0]), e11 = fexp8(acc[2 * u + 1][1]);
            float e12 = fexp8(acc[2 * u + 1][2]), e13 = fexp8(acc[2 * u + 1][3]);
            z1[0] += e00 + e01 + e10 + e11;
            z1[1] += e02 + e03 + e12 + e13;
            float2 q0 = __half22float2(*(half2*)&ea0[u][0]);
            float2 q1 = __half22float2(*(half2*)&ea0[u][1]);
            float2 q2 = __half22float2(*(half2*)&ea0[u][2]);
            float2 q3 = __half22float2(*(half2*)&ea0[u][3]);
            dt[0] += q0.x * e00 + q0.y * e01 + q2.x * e10 + q2.y * e11;
            dt[1] += q1.x * e02 + q1.y * e03 + q3.x * e12 + q3.y * e13;
            ea1[u][0] = pack_h2(e00, e01);
            ea1[u][1] = pack_h2(e02, e03);
            ea1[u][2] = pack_h2(e10, e11);
            ea1[u][3] = pack_h2(e12, e13);
        }
        // ---------- AV branch 1 ----------
#pragma unroll
        for (int u = 0; u < 2; u++) {
            int koff = h * 64 + u * 32;
#pragma unroll
            for (int j2 = 0; j2 < 4; j2++) {
                uint32_t b0, b1, b2, b3;
                ldsm4(b0, b1, b2, b3, vB1 + (j2 * 16 + al) * 128 + (((koff + seg0 * 16)) ^ aswz));
                mma16(O1[2 * j2],     ea1[u][0], ea1[u][1], ea1[u][2], ea1[u][3], b0, b2);
                mma16(O1[2 * j2 + 1], ea1[u][0], ea1[u][1], ea1[u][2], ea1[u][3], b1, b3);
            }
        }
        __syncthreads();
        if (jt + 2 < 16) {
            int j0 = (jt + 2) * 64;
            issue_kv(smb, ASK0 + cb, ASV0 + cb, Kh0, Vt0, j0, tid);
            issue_kv(smb, ASK1 + cb, ASV1 + cb, Kh1, Vt1, j0, tid);
            CPCOMMIT();
        }
    }

    // ---------- epilogue: quad-reduce, pair-combine z/dt + O, store ----------
#pragma unroll
    for (int hh2 = 0; hh2 < 2; hh2++) {
        z0[hh2] += __shfl_xor_sync(0xffffffffu, z0[hh2], 1); z0[hh2] += __shfl_xor_sync(0xffffffffu, z0[hh2], 2);
        z1[hh2] += __shfl_xor_sync(0xffffffffu, z1[hh2], 1); z1[hh2] += __shfl_xor_sync(0xffffffffu, z1[hh2], 2);
        dt[hh2] += __shfl_xor_sync(0xffffffffu, dt[hh2], 1); dt[hh2] += __shfl_xor_sync(0xffffffffu, dt[hh2], 2);
    }
    const int r1 = wm * 16 + g, r2 = r1 + 8;
    float* stage = (float*)smch;                 // 16KB O staging (Q dead)
    float* zz0 = (float*)(smch + 16384);         // K area dead
    float* zz1 = zz0 + 64;
    float* dd  = zz0 + 128;
    if (h == 0 && tig == 0) {
        zz0[r1] = z0[0]; zz0[r2] = z0[1];
        zz1[r1] = z1[0]; zz1[r2] = z1[1];
        dd[r1]  = dt[0]; dd[r2]  = dt[1];
    }
    float* sp = stage + wm * 1024;
    if (h == 0) {
#pragma unroll
        for (int nt = 0; nt < 8; nt++) {
            int dcol = nt * 8 + 2 * tig;
            sp[g * 64 + dcol]           = O0[nt][0];
            sp[g * 64 + dcol + 1]       = O0[nt][1];
            sp[(g + 8) * 64 + dcol]     = O0[nt][2];
            sp[(g + 8) * 64 + dcol + 1] = O0[nt][3];
        }
    }
    __syncthreads();
    float temp = fminf(fmaxf(*temp_ptr, 0.1f), 5.0f);
    int bidx = head / 12, hd = head - bidx * 12;
    int n1 = i0 + r1;
    float c0r[2], c1r[2];
    if (h == 1) {
#pragma unroll
        for (int hh2 = 0; hh2 < 2; hh2++) {
            int rr = hh2 ? r2 : r1;
            float a = zz0[rr] + z0[hh2];
            float b = zz1[rr] + z1[hh2];
            float d = dd[rr] + dt[hh2];
            float overlap = d / (a * b) + 2.0f * EPSF + 1024.0f * EPSF * EPSF;
            float mask = 1.0f / (1.0f + __expf(overlap * temp));
            float f = mask / (mask + EPSF);
            c0r[hh2] = f / a;
            c1r[hh2] = f / b;
        }
        __half* p1a = g_aoh[0] + ((size_t)(bidx * 1024 + n1)) * 768 + hd * 64 + 2 * tig;
        __half* p2a = g_aoh[0] + ((size_t)(bidx * 1024 + n1 + 8)) * 768 + hd * 64 + 2 * tig;
#pragma unroll
        for (int nt = 0; nt < 8; nt++) {
            int dcol = nt * 8 + 2 * tig;
            float o0 = O0[nt][0] + sp[g * 64 + dcol];
            float o1 = O0[nt][1] + sp[g * 64 + dcol + 1];
            float o2 = O0[nt][2] + sp[(g + 8) * 64 + dcol];
            float o3 = O0[nt][3] + sp[(g + 8) * 64 + dcol + 1];
            *(half2*)(p1a + nt * 8) = __floats2half2_rn(o0 * c0r[0], o1 * c0r[0]);
            *(half2*)(p2a + nt * 8) = __floats2half2_rn(o2 * c0r[1], o3 * c0r[1]);
        }
    }
    __syncthreads();
    if (h == 0) {
#pragma unroll
        for (int nt = 0; nt < 8; nt++) {
            int dcol = nt * 8 + 2 * tig;
            sp[g * 64 + dcol]           = O1[nt][0];
            sp[g * 64 + dcol + 1]       = O1[nt][1];
            sp[(g + 8) * 64 + dcol]     = O1[nt][2];
            sp[(g + 8) * 64 + dcol + 1] = O1[nt][3];
        }
    }
    __syncthreads();
    if (h == 1) {
        __half* p1b = g_aoh[1] + ((size_t)(bidx * 1024 + n1)) * 768 + hd * 64 + 2 * tig;
        __half* p2b = g_aoh[1] + ((size_t)(bidx * 1024 + n1 + 8)) * 768 + hd * 64 + 2 * tig;
#pragma unroll
        for (int nt = 0; nt < 8; nt++) {
            int dcol = nt * 8 + 2 * tig;
            float o0 = O1[nt][0] + sp[g * 64 + dcol];
            float o1 = O1[nt][1] + sp[g * 64 + dcol + 1];
            float o2 = O1[nt][2] + sp[(g + 8) * 64 + dcol];
            float o3 = O1[nt][3] + sp[(g + 8) * 64 + dcol + 1];
            *(half2*)(p1b + nt * 8) = __floats2half2_rn(o0 * c1r[0], o1 * c1r[0]);
            *(half2*)(p2b + nt * 8) = __floats2half2_rn(o2 * c1r[1], o3 * c1r[1]);
        }
    }
}

// ================= 0a) weight transpose pair -> fp16 ========================
__global__ __launch_bounds__(256) void k_tr2h(const float* __restrict__ in0,
                                              const float* __restrict__ in1,
                                              __half* __restrict__ out0,
                                              __half* __restrict__ out1, int R, int C) {
    __shared__ float t[32][33];
    const float* in = blockIdx.z ? in1 : in0;
    __half* out = blockIdx.z ? out1 : out0;
    int bx = blockIdx.x * 32, by = blockIdx.y * 32;
    int x = threadIdx.x & 31, y = threadIdx.x >> 5;
#pragma unroll
    for (int j = 0; j < 32; j += 8) t[y + j][x] = in[(size_t)(by + y + j) * C + bx + x];
    __syncthreads();
#pragma unroll
    for (int j = 0; j < 32; j += 8) out[(size_t)(bx + y + j) * R + by + x] = __float2half_rn(t[x][y + j]);
}

// ================= 0b) x -> fp16 ============================================
__global__ __launch_bounds__(256) void k_rxh(const float* __restrict__ x,
                                             __half* __restrict__ o) {
    int i = blockIdx.x * 256 + threadIdx.x;
    float4 v = ((const float4*)x)[i];
    ((half2*)o)[2 * i]     = __floats2half2_rn(v.x, v.y);
    ((half2*)o)[2 * i + 1] = __floats2half2_rn(v.z, v.w);
}

// ================= 5) LayerNorm over C=768 from fp16 pre-LN =================
__device__ __forceinline__ float blk_reduce(float v, float* smr) {
    const unsigned full = 0xffffffffu;
#pragma unroll
    for (int o = 16; o > 0; o >>= 1) v += __shfl_xor_sync(full, v, o);
    int warp = threadIdx.x >> 5, lane = threadIdx.x & 31;
    if (lane == 0) smr[warp] = v;
    __syncthreads();
    if (warp == 0) {
        float x = (lane < 8) ? smr[lane] : 0.0f;
#pragma unroll
        for (int o = 4; o > 0; o >>= 1) x += __shfl_xor_sync(full, x, o);
        if (lane == 0) smr[0] = x;
    }
    __syncthreads();
    float r = smr[0];
    __syncthreads();
    return r;
}

__global__ __launch_bounds__(256) void k_ln(const float* __restrict__ g0,
                                            const float* __restrict__ b0,
                                            const float* __restrict__ g1,
                                            const float* __restrict__ b1,
                                            float* __restrict__ out) {
    __shared__ float smr[32];
    int br = blockIdx.y;
    int row = blockIdx.x;
    const float* gam = br ? g1 : g0;
    const float* bet = br ? b1 : b0;
    float* o = out + (size_t)br * Mm * Cc;
    const __half* x = g_prh[br] + (size_t)row * Cc;
    int t = threadIdx.x;
    // 384 half2 per row: thread t owns h2[t]; threads t<128 also own h2[256+t]
    float2 va = __half22float2(((const half2*)x)[t]);
    float2 vb = make_float2(0.f, 0.f);
    bool hasb = t < 128;
    if (hasb) vb = __half22float2(((const half2*)x)[256 + t]);
    float s = va.x + va.y + vb.x + vb.y;
    s = blk_reduce(s, smr);
    float mu = s * (1.0f / (float)Cc);
    float d0 = va.x - mu, d1 = va.y - mu;
    float ss = d0 * d0 + d1 * d1;
    if (hasb) { float d2 = vb.x - mu, d3 = vb.y - mu; ss += d2 * d2 + d3 * d3; }
    ss = blk_reduce(ss, smr);
    float inv = rsqrtf(ss * (1.0f / (float)Cc) + LNEPS);
    float2 ga = ((const float2*)gam)[t];
    float2 ba = ((const float2*)bet)[t];
    ((float2*)(o + (size_t)row * Cc))[t] =
        make_float2(d0 * inv * ga.x + ba.x, d1 * inv * ga.y + ba.y);
    if (hasb) {
        float2 gb = ((const float2*)gam)[256 + t];
        float2 bb = ((const float2*)bet)[256 + t];
        ((float2*)(o + (size_t)row * Cc))[256 + t] =
            make_float2((vb.x - mu) * inv * gb.x + bb.x, (vb.y - mu) * inv * gb.y + bb.y);
    }
}

// ================= launch ==================================================
extern "C" void kernel_launch(void* const* d_in, const int* in_sizes, int n_in,
                              void* d_out, int out_size) {
    const float* x    = (const float*)d_in[0];
    const float* wq0  = (const float*)d_in[1];
    const float* wq1  = (const float*)d_in[2];
    const float* wp0  = (const float*)d_in[3];
    const float* bp0  = (const float*)d_in[4];
    const float* wp1  = (const float*)d_in[5];
    const float* bp1  = (const float*)d_in[6];
    const float* temp = (const float*)d_in[7];
    const float* g0   = (const float*)d_in[8];
    const float* b0   = (const float*)d_in[9];
    const float* g1   = (const float*)d_in[10];
    const float* b1   = (const float*)d_in[11];
    float* out = (float*)d_out;

    static __half* wt0 = nullptr; static __half* wt1 = nullptr;
    static __half* wpt0 = nullptr; static __half* wpt1 = nullptr;
    static __half* xr = nullptr;
    if (!wt0) {
        cudaGetSymbolAddress((void**)&wt0, g_wth);
        wt1 = wt0 + (size_t)3 * Cc * Cc;
        cudaGetSymbolAddress((void**)&wpt0, g_wpth);
        wpt1 = wpt0 + (size_t)Cc * Cc;
        cudaGetSymbolAddress((void**)&xr, g_xrh);
        cudaFuncSetAttribute(k_qkv_mma, cudaFuncAttributeMaxDynamicSharedMemorySize, 65536);
        cudaFuncSetAttribute(k_proj_mma, cudaFuncAttributeMaxDynamicSharedMemorySize, 65536);
        cudaFuncSetAttribute(k_attn, cudaFuncAttributeMaxDynamicSharedMemorySize, A_SMEM);
    }

    dim3 t256(256);
    k_tr2h<<<dim3(72, 24, 2), t256>>>(wq0, wq1, wt0, wt1, 768, 2304);
    k_tr2h<<<dim3(24, 24, 2), t256>>>(wp0, wp1, wpt0, wpt1, 768, 768);
    k_rxh<<<dim3(6144), t256>>>(x, xr);

    k_qkv_mma<<<dim3(18, 64, 2), t256, 65536>>>(xr, wt0, wt1);
    k_attn<<<dim3(16, BHh), t256, A_SMEM>>>(temp);
    k_proj_mma<<<dim3(6, 64, 2), t256, 65536>>>(wpt0, wpt1, bp0, bp1);
    k_ln<<<dim3(Mm, 2), t256>>>(g0, b0, g1, b1, out);
}